// round 1
// baseline (speedup 1.0000x reference)
#include <cuda_runtime.h>
#include <math.h>

// ---------------- problem constants ----------------
#define BATCHN  4
#define SEQLEN  2048
#define DMODEL  512
#define DINNER  1024
#define NHEADSN 16
#define HEADDIM 64
#define DSTATE  64
#define CONVDIM 1152
#define DINPROJ 2208
#define DFF     2048
#define NROWS   (BATCHN*SEQLEN)   // 8192
#define EPSV    1e-5f

// ---------------- scratch (device globals; no allocation allowed) ----------------
__device__ float g_h   [NROWS*DMODEL];        // ln1 / ln2 output (reused)
__device__ float g_zx  [NROWS*DINPROJ];       // in_proj output
__device__ float g_xbc [NROWS*CONVDIM];       // conv+silu output
__device__ float g_dec [8*SEQLEN*NHEADSN];    // decay, indexed by ORIGINAL time
__device__ float g_dts [8*SEQLEN*NHEADSN];    // softplus(dt), indexed by ORIGINAL time
__device__ float g_y   [8*SEQLEN*DINNER];     // scan outputs (fw: s=0..3, bw: s=4..7), already shifted
__device__ float g_yg  [NROWS*DINNER];        // gated+rms-normed
__device__ float g_x2  [NROWS*DMODEL];        // x + hydra_out
__device__ float g_ff1 [NROWS*DFF];           // gelu(fc1)

// ---------------- helpers ----------------
__device__ __forceinline__ float geluf(float x) {
    return 0.5f * x * (1.0f + erff(x * 0.70710678118654752f));
}
__device__ __forceinline__ float siluf(float x) {
    return x / (1.0f + expf(-x));
}

// ---------------- LayerNorm (D=512), one block of 128 threads per row ----------------
__global__ void __launch_bounds__(128) ln_kernel(
    const float* __restrict__ x, const float* __restrict__ w,
    const float* __restrict__ b, float* __restrict__ out)
{
    int row = blockIdx.x;
    int tid = threadIdx.x;
    const float4 v = ((const float4*)(x + (size_t)row*DMODEL))[tid];
    float s  = v.x + v.y + v.z + v.w;
    float ss = v.x*v.x + v.y*v.y + v.z*v.z + v.w*v.w;
    #pragma unroll
    for (int o = 16; o > 0; o >>= 1) {
        s  += __shfl_xor_sync(0xffffffffu, s,  o);
        ss += __shfl_xor_sync(0xffffffffu, ss, o);
    }
    __shared__ float as[4], ass[4];
    int wid = tid >> 5;
    if ((tid & 31) == 0) { as[wid] = s; ass[wid] = ss; }
    __syncthreads();
    s  = as[0] + as[1] + as[2] + as[3];
    ss = ass[0] + ass[1] + ass[2] + ass[3];
    float mean = s * (1.0f/DMODEL);
    float var  = ss * (1.0f/DMODEL) - mean*mean;
    float rstd = rsqrtf(var + EPSV);
    const float4 wv = ((const float4*)w)[tid];
    const float4 bv = ((const float4*)b)[tid];
    float4 o;
    o.x = (v.x - mean)*rstd*wv.x + bv.x;
    o.y = (v.y - mean)*rstd*wv.y + bv.y;
    o.z = (v.z - mean)*rstd*wv.z + bv.z;
    o.w = (v.w - mean)*rstd*wv.w + bv.w;
    ((float4*)(out + (size_t)row*DMODEL))[tid] = o;
}

// ---------------- SGEMM: C[M,N] = A[M,K] @ W[N,K]^T  (+ epilogue) ----------------
// EPI: 0 = none, 1 = +bias,gelu, 2 = +res, 3 = +bias +res
template<int EPI>
__global__ void __launch_bounds__(256) gemm_kernel(
    const float* __restrict__ A, const float* __restrict__ W,
    const float* __restrict__ bias, const float* __restrict__ res,
    float* __restrict__ C, int M, int N, int K)
{
    const int BM = 128, BN = 64, BK = 16;
    __shared__ float As[BK][BM+4];
    __shared__ float Bs[BK][BN+4];
    int bm = blockIdx.y * BM, bn = blockIdx.x * BN;
    int tid = threadIdx.x;
    int tx = tid & 15;   // n dir (16 * 4 = 64)
    int ty = tid >> 4;   // m dir (16 * 8 = 128)
    float acc[8][4];
    #pragma unroll
    for (int i = 0; i < 8; i++)
        #pragma unroll
        for (int j = 0; j < 4; j++) acc[i][j] = 0.f;

    int a_row = tid >> 2;            // 0..63
    int a_col = (tid & 3) << 2;      // 0,4,8,12

    for (int k0 = 0; k0 < K; k0 += BK) {
        #pragma unroll
        for (int rr = 0; rr < 2; rr++) {
            int r = a_row + rr*64;
            const float4 v = *(const float4*)&A[(size_t)(bm + r)*K + k0 + a_col];
            As[a_col+0][r] = v.x; As[a_col+1][r] = v.y;
            As[a_col+2][r] = v.z; As[a_col+3][r] = v.w;
        }
        {
            int n = bn + a_row;
            float4 v = make_float4(0.f, 0.f, 0.f, 0.f);
            if (n < N) v = *(const float4*)&W[(size_t)n*K + k0 + a_col];
            Bs[a_col+0][a_row] = v.x; Bs[a_col+1][a_row] = v.y;
            Bs[a_col+2][a_row] = v.z; Bs[a_col+3][a_row] = v.w;
        }
        __syncthreads();
        #pragma unroll
        for (int k = 0; k < BK; k++) {
            const float4* ap = (const float4*)&As[k][ty << 3];
            float4 a0 = ap[0], a1 = ap[1];
            float4 b0 = *(const float4*)&Bs[k][tx << 2];
            float av[8] = {a0.x,a0.y,a0.z,a0.w,a1.x,a1.y,a1.z,a1.w};
            float bv[4] = {b0.x,b0.y,b0.z,b0.w};
            #pragma unroll
            for (int i = 0; i < 8; i++)
                #pragma unroll
                for (int j = 0; j < 4; j++)
                    acc[i][j] = fmaf(av[i], bv[j], acc[i][j]);
        }
        __syncthreads();
    }

    int n0 = bn + (tx << 2);
    if (n0 < N) {
        float4 bv = make_float4(0.f,0.f,0.f,0.f);
        if (EPI == 1 || EPI == 3) bv = *(const float4*)&bias[n0];
        #pragma unroll
        for (int i = 0; i < 8; i++) {
            int m = bm + (ty << 3) + i;
            float4 o = make_float4(acc[i][0], acc[i][1], acc[i][2], acc[i][3]);
            if (EPI == 1) {
                o.x = geluf(o.x + bv.x); o.y = geluf(o.y + bv.y);
                o.z = geluf(o.z + bv.z); o.w = geluf(o.w + bv.w);
            }
            if (EPI == 2) {
                const float4 r = *(const float4*)&res[(size_t)m*N + n0];
                o.x += r.x; o.y += r.y; o.z += r.z; o.w += r.w;
            }
            if (EPI == 3) {
                const float4 r = *(const float4*)&res[(size_t)m*N + n0];
                o.x += r.x + bv.x; o.y += r.y + bv.y;
                o.z += r.z + bv.z; o.w += r.w + bv.w;
            }
            *(float4*)&C[(size_t)m*N + n0] = o;
        }
    }
}

// ---------------- dt preprocess: decay & softplus(dt), indexed by original t ----------------
__global__ void dt_kernel(const float* __restrict__ zx, const float* __restrict__ dt_bias,
                          const float* __restrict__ A_log,
                          float* __restrict__ dec, float* __restrict__ dts)
{
    int idx = blockIdx.x * blockDim.x + threadIdx.x;  // ((s*L)+t)*16 + h
    int hh = idx & 15;
    int t  = (idx >> 4) & (SEQLEN - 1);
    int s  = idx >> 15;
    int b  = s & 3;
    int off = (s < 4) ? 0 : NHEADSN;
    float raw = zx[((size_t)b*SEQLEN + t)*DINPROJ + (DINNER + CONVDIM) + off + hh] + dt_bias[hh];
    float sp = (raw > 20.f) ? raw : log1pf(expf(raw));
    float Ah = -expf(A_log[hh]);
    dec[idx] = expf(Ah * sp);
    dts[idx] = sp;
}

// ---------------- depthwise causal conv7 + bias + silu ----------------
__global__ void conv_kernel(const float* __restrict__ zx, const float* __restrict__ cw,
                            const float* __restrict__ cb, float* __restrict__ out)
{
    int idx = blockIdx.x * blockDim.x + threadIdx.x;  // (b*L+t)*1152 + c
    int c  = idx % CONVDIM;
    int bt = idx / CONVDIM;
    int t  = bt & (SEQLEN - 1);
    int b  = bt >> 11;
    float acc = cb[c];
    #pragma unroll
    for (int j = 0; j < 7; j++) {
        int tt = t - 6 + j;
        if (tt >= 0)
            acc = fmaf(zx[((size_t)b*SEQLEN + tt)*DINPROJ + DINNER + c], cw[c*7 + j], acc);
    }
    out[idx] = siluf(acc);
}

// ---------------- bidirectional SSM scan ----------------
// grid = (heads=16, seqs=8). 256 threads: thread = (p = tid/4, quarter q = tid%4),
// each thread owns 16 state elems (n = q*16 .. q*16+15) in registers.
// Output written pre-shifted: fw stores at t+1 (zero at 0), bw stores at t-1 (zero at L-1).
__global__ void __launch_bounds__(256) scan_kernel(
    const float* __restrict__ xbc, const float* __restrict__ dec,
    const float* __restrict__ dts, float* __restrict__ y)
{
    const int h = blockIdx.x;
    const int s = blockIdx.y;
    const int b = s & 3;
    const bool fw = (s < 4);
    const int tid = threadIdx.x;
    const int p = tid >> 2;
    const int q = tid & 3;

    __shared__ float sB[16][64], sC[16][64], sX[16][64];
    __shared__ float sDec[16], sDt[16];

    float hreg[16];
    #pragma unroll
    for (int i = 0; i < 16; i++) hreg[i] = 0.f;

    const float* base = xbc + (size_t)b*SEQLEN*CONVDIM;
    float* yout = y + (size_t)s*SEQLEN*DINNER + h*HEADDIM + p;

    if (q == 0) {
        int t0 = fw ? 0 : (SEQLEN - 1);
        yout[(size_t)t0*DINNER] = 0.f;   // shifted-out position
    }

    for (int cc = 0; cc < SEQLEN/16; cc++) {
        // cooperative chunk load (16 steps of x-head, B, C + scalars)
        for (int i = tid; i < 16*64; i += 256) {
            int j = i >> 6, n = i & 63;
            int tau = cc*16 + j;
            int orig = fw ? tau : (SEQLEN - 1 - tau);
            const float* row = base + (size_t)orig*CONVDIM;
            sX[j][n] = row[h*HEADDIM + n];
            sB[j][n] = row[DINNER + n];
            sC[j][n] = row[DINNER + DSTATE + n];
        }
        if (tid < 16) {
            int tau = cc*16 + tid;
            int orig = fw ? tau : (SEQLEN - 1 - tau);
            size_t di = ((size_t)s*SEQLEN + orig)*NHEADSN + h;
            sDec[tid] = dec[di];
            sDt[tid]  = dts[di];
        }
        __syncthreads();

        #pragma unroll 4
        for (int j = 0; j < 16; j++) {
            float d  = sDec[j];
            float dtv = sDt[j];
            float dtx = dtv * sX[j][p];
            const float4* B4 = (const float4*)&sB[j][q << 4];
            const float4* C4 = (const float4*)&sC[j][q << 4];
            float ysum = 0.f;
            #pragma unroll
            for (int v = 0; v < 4; v++) {
                float4 bb = B4[v], cv = C4[v];
                hreg[v*4+0] = fmaf(hreg[v*4+0], d, dtx*bb.x); ysum = fmaf(hreg[v*4+0], cv.x, ysum);
                hreg[v*4+1] = fmaf(hreg[v*4+1], d, dtx*bb.y); ysum = fmaf(hreg[v*4+1], cv.y, ysum);
                hreg[v*4+2] = fmaf(hreg[v*4+2], d, dtx*bb.z); ysum = fmaf(hreg[v*4+2], cv.z, ysum);
                hreg[v*4+3] = fmaf(hreg[v*4+3], d, dtx*bb.w); ysum = fmaf(hreg[v*4+3], cv.w, ysum);
            }
            ysum += __shfl_xor_sync(0xffffffffu, ysum, 1);
            ysum += __shfl_xor_sync(0xffffffffu, ysum, 2);
            if (q == 0) {
                int tau = cc*16 + j;
                int to = fw ? (tau + 1) : (SEQLEN - 2 - tau);
                if (to >= 0 && to < SEQLEN)
                    yout[(size_t)to*DINNER] = ysum;
            }
        }
        __syncthreads();
    }
}

// ---------------- gating + D skip + RMS norm ----------------
__global__ void __launch_bounds__(256) gate_rms_kernel(
    const float* __restrict__ y, const float* __restrict__ xbc,
    const float* __restrict__ zx, const float* __restrict__ Dp,
    const float* __restrict__ rms_w, float* __restrict__ out)
{
    int row = blockIdx.x;
    int b = row >> 11, t = row & 2047;
    int c = threadIdx.x << 2;
    size_t ybase = ((size_t)b*SEQLEN + t)*DINNER + c;
    const float4 yf = *(const float4*)&y[ybase];
    const float4 yb = *(const float4*)&y[ybase + (size_t)4*SEQLEN*DINNER];
    const float4 xo = *(const float4*)&xbc[((size_t)b*SEQLEN + t)*CONVDIM + c];
    const float4 zv = *(const float4*)&zx[((size_t)b*SEQLEN + t)*DINPROJ + c];
    float dp = Dp[c >> 6];
    float g0 = (yf.x + yb.x + xo.x*dp) * siluf(zv.x);
    float g1 = (yf.y + yb.y + xo.y*dp) * siluf(zv.y);
    float g2 = (yf.z + yb.z + xo.z*dp) * siluf(zv.z);
    float g3 = (yf.w + yb.w + xo.w*dp) * siluf(zv.w);
    float ss = g0*g0 + g1*g1 + g2*g2 + g3*g3;
    #pragma unroll
    for (int o = 16; o > 0; o >>= 1)
        ss += __shfl_xor_sync(0xffffffffu, ss, o);
    __shared__ float asum[8];
    int wid = threadIdx.x >> 5;
    if ((threadIdx.x & 31) == 0) asum[wid] = ss;
    __syncthreads();
    ss = asum[0]+asum[1]+asum[2]+asum[3]+asum[4]+asum[5]+asum[6]+asum[7];
    float scale = rsqrtf(ss * (1.0f/DINNER) + EPSV);
    const float4 wv = *(const float4*)&rms_w[c];
    float4 o;
    o.x = g0*scale*wv.x; o.y = g1*scale*wv.y;
    o.z = g2*scale*wv.z; o.w = g3*scale*wv.w;
    *(float4*)&out[(size_t)row*DINNER + c] = o;
}

// ---------------- launcher ----------------
extern "C" void kernel_launch(void* const* d_in, const int* in_sizes, int n_in,
                              void* d_out, int out_size)
{
    const float* x         = (const float*)d_in[0];
    const float* ln1_w     = (const float*)d_in[1];
    const float* ln1_b     = (const float*)d_in[2];
    const float* in_proj_w = (const float*)d_in[3];
    const float* conv_w    = (const float*)d_in[4];
    const float* conv_b    = (const float*)d_in[5];
    const float* dt_bias   = (const float*)d_in[6];
    const float* A_log     = (const float*)d_in[7];
    const float* Dp        = (const float*)d_in[8];
    const float* rms_w     = (const float*)d_in[9];
    const float* out_proj_w= (const float*)d_in[10];
    const float* ln2_w     = (const float*)d_in[11];
    const float* ln2_b     = (const float*)d_in[12];
    const float* fc1_w     = (const float*)d_in[13];
    const float* fc1_b     = (const float*)d_in[14];
    const float* fc2_w     = (const float*)d_in[15];
    const float* fc2_b     = (const float*)d_in[16];
    float* out = (float*)d_out;

    float *h, *zx, *xbc, *dec, *dts, *y, *yg, *x2, *ff1;
    cudaGetSymbolAddress((void**)&h,   g_h);
    cudaGetSymbolAddress((void**)&zx,  g_zx);
    cudaGetSymbolAddress((void**)&xbc, g_xbc);
    cudaGetSymbolAddress((void**)&dec, g_dec);
    cudaGetSymbolAddress((void**)&dts, g_dts);
    cudaGetSymbolAddress((void**)&y,   g_y);
    cudaGetSymbolAddress((void**)&yg,  g_yg);
    cudaGetSymbolAddress((void**)&x2,  g_x2);
    cudaGetSymbolAddress((void**)&ff1, g_ff1);

    // 1. LN1
    ln_kernel<<<NROWS, 128>>>(x, ln1_w, ln1_b, h);
    // 2. in_proj: [8192,512] @ [2208,512]^T
    gemm_kernel<0><<<dim3((DINPROJ + 63)/64, NROWS/128), 256>>>(
        h, in_proj_w, nullptr, nullptr, zx, NROWS, DINPROJ, DMODEL);
    // 3. dt preprocess
    dt_kernel<<<(8*SEQLEN*NHEADSN)/256, 256>>>(zx, dt_bias, A_log, dec, dts);
    // 4. conv + silu
    conv_kernel<<<(NROWS*CONVDIM)/256, 256>>>(zx, conv_w, conv_b, xbc);
    // 5. bidirectional SSM scan
    scan_kernel<<<dim3(NHEADSN, 8), 256>>>(xbc, dec, dts, y);
    // 6. gate + D skip + RMS norm
    gate_rms_kernel<<<NROWS, 256>>>(y, xbc, zx, Dp, rms_w, yg);
    // 7. out_proj + residual(x): [8192,1024] @ [512,1024]^T
    gemm_kernel<2><<<dim3(DMODEL/64, NROWS/128), 256>>>(
        yg, out_proj_w, nullptr, x, x2, NROWS, DMODEL, DINNER);
    // 8. LN2
    ln_kernel<<<NROWS, 128>>>(x2, ln2_w, ln2_b, h);
    // 9. fc1 + bias + gelu: [8192,512] @ [2048,512]^T
    gemm_kernel<1><<<dim3(DFF/64, NROWS/128), 256>>>(
        h, fc1_w, fc1_b, nullptr, ff1, NROWS, DFF, DMODEL);
    // 10. fc2 + bias + residual(x2): [8192,2048] @ [512,2048]^T -> d_out
    gemm_kernel<3><<<dim3(DMODEL/64, NROWS/128), 256>>>(
        ff1, fc2_w, fc2_b, x2, out, NROWS, DMODEL, DFF);
}

// round 2
// speedup vs baseline: 1.5750x; 1.5750x over previous
#include <cuda_runtime.h>
#include <math.h>
#include <stdint.h>

// ---------------- problem constants ----------------
#define BATCHN  4
#define SEQLEN  2048
#define DMODEL  512
#define DINNER  1024
#define NHEADSN 16
#define HEADDIM 64
#define DSTATE  64
#define CONVDIM 1152
#define DINPROJ 2208
#define DFF     2048
#define NROWS   (BATCHN*SEQLEN)   // 8192
#define EPSV    1e-5f

// ---------------- scratch (device globals; no allocation allowed) ----------------
__device__ float g_h   [NROWS*DMODEL];
__device__ float g_zx  [NROWS*DINPROJ];
__device__ float g_xbc [NROWS*CONVDIM];
__device__ float g_dec [8*SEQLEN*NHEADSN];
__device__ float g_dts [8*SEQLEN*NHEADSN];
__device__ float g_y   [8*SEQLEN*DINNER];
__device__ float g_yg  [NROWS*DINNER];
__device__ float g_x2  [NROWS*DMODEL];
__device__ float g_ff1 [NROWS*DFF];

// ---------------- helpers ----------------
__device__ __forceinline__ float geluf(float x) {
    return 0.5f * x * (1.0f + erff(x * 0.70710678118654752f));
}
__device__ __forceinline__ float siluf(float x) {
    return x / (1.0f + expf(-x));
}
__device__ __forceinline__ uint32_t f2tf32(float x) {
    uint32_t r;
    asm("cvt.rna.tf32.f32 %0, %1;" : "=r"(r) : "f"(x));
    return r;
}

// ---------------- LayerNorm (D=512) ----------------
__global__ void __launch_bounds__(128) ln_kernel(
    const float* __restrict__ x, const float* __restrict__ w,
    const float* __restrict__ b, float* __restrict__ out)
{
    int row = blockIdx.x;
    int tid = threadIdx.x;
    const float4 v = ((const float4*)(x + (size_t)row*DMODEL))[tid];
    float s  = v.x + v.y + v.z + v.w;
    float ss = v.x*v.x + v.y*v.y + v.z*v.z + v.w*v.w;
    #pragma unroll
    for (int o = 16; o > 0; o >>= 1) {
        s  += __shfl_xor_sync(0xffffffffu, s,  o);
        ss += __shfl_xor_sync(0xffffffffu, ss, o);
    }
    __shared__ float as[4], ass[4];
    int wid = tid >> 5;
    if ((tid & 31) == 0) { as[wid] = s; ass[wid] = ss; }
    __syncthreads();
    s  = as[0] + as[1] + as[2] + as[3];
    ss = ass[0] + ass[1] + ass[2] + ass[3];
    float mean = s * (1.0f/DMODEL);
    float var  = ss * (1.0f/DMODEL) - mean*mean;
    float rstd = rsqrtf(var + EPSV);
    const float4 wv = ((const float4*)w)[tid];
    const float4 bv = ((const float4*)b)[tid];
    float4 o;
    o.x = (v.x - mean)*rstd*wv.x + bv.x;
    o.y = (v.y - mean)*rstd*wv.y + bv.y;
    o.z = (v.z - mean)*rstd*wv.z + bv.z;
    o.w = (v.w - mean)*rstd*wv.w + bv.w;
    ((float4*)(out + (size_t)row*DMODEL))[tid] = o;
}

// ---------------- TF32 tensor-core GEMM: C[M,N] = A[M,K] @ W[N,K]^T (+epilogue) ----------------
// EPI: 0 = none, 1 = +bias,gelu, 2 = +res, 3 = +bias +res
// Block tile 128x128x16; 8 warps, each 64x32; mma.m16n8k8 tf32.
template<int EPI>
__global__ void __launch_bounds__(256) gemm_tc(
    const float* __restrict__ A, const float* __restrict__ W,
    const float* __restrict__ bias, const float* __restrict__ res,
    float* __restrict__ C, int M, int N, int K)
{
    constexpr int BK = 16, LDSW = BK + 4;   // stride 20 words -> conflict-free frags
    __shared__ uint32_t As[128 * LDSW];
    __shared__ uint32_t Bs[128 * LDSW];

    const int tid  = threadIdx.x;
    const int wid  = tid >> 5, lane = tid & 31;
    const int wm   = (wid >> 2) << 6;     // 0 / 64
    const int wn   = (wid & 3)  << 5;     // 0,32,64,96
    const int g    = lane >> 2, tg = lane & 3;
    const int bm   = blockIdx.y << 7, bn = blockIdx.x << 7;

    const int ldr = tid >> 2;             // 0..63
    const int ldc = (tid & 3) << 2;       // 0,4,8,12
    const int n0g = bn + ldr, n1g = bn + ldr + 64;

    float acc[16][4];
    #pragma unroll
    for (int i = 0; i < 16; i++) { acc[i][0]=acc[i][1]=acc[i][2]=acc[i][3]=0.f; }

    float4 ra0, ra1, rb0, rb1;

    // prologue load (k0 = 0)
    {
        ra0 = *(const float4*)&A[(size_t)(bm + ldr)*K + ldc];
        ra1 = *(const float4*)&A[(size_t)(bm + ldr + 64)*K + ldc];
        rb0 = (n0g < N) ? *(const float4*)&W[(size_t)n0g*K + ldc] : make_float4(0,0,0,0);
        rb1 = (n1g < N) ? *(const float4*)&W[(size_t)n1g*K + ldc] : make_float4(0,0,0,0);
    }

    for (int k0 = 0; k0 < K; k0 += BK) {
        // stage regs -> smem (convert to tf32 once here)
        {
            uint32_t* p = &As[ldr*LDSW + ldc];
            p[0]=f2tf32(ra0.x); p[1]=f2tf32(ra0.y); p[2]=f2tf32(ra0.z); p[3]=f2tf32(ra0.w);
            p = &As[(ldr+64)*LDSW + ldc];
            p[0]=f2tf32(ra1.x); p[1]=f2tf32(ra1.y); p[2]=f2tf32(ra1.z); p[3]=f2tf32(ra1.w);
            p = &Bs[ldr*LDSW + ldc];
            p[0]=f2tf32(rb0.x); p[1]=f2tf32(rb0.y); p[2]=f2tf32(rb0.z); p[3]=f2tf32(rb0.w);
            p = &Bs[(ldr+64)*LDSW + ldc];
            p[0]=f2tf32(rb1.x); p[1]=f2tf32(rb1.y); p[2]=f2tf32(rb1.z); p[3]=f2tf32(rb1.w);
        }
        __syncthreads();

        // prefetch next tile
        if (k0 + BK < K) {
            int kn = k0 + BK;
            ra0 = *(const float4*)&A[(size_t)(bm + ldr)*K + kn + ldc];
            ra1 = *(const float4*)&A[(size_t)(bm + ldr + 64)*K + kn + ldc];
            rb0 = (n0g < N) ? *(const float4*)&W[(size_t)n0g*K + kn + ldc] : make_float4(0,0,0,0);
            rb1 = (n1g < N) ? *(const float4*)&W[(size_t)n1g*K + kn + ldc] : make_float4(0,0,0,0);
        }

        // compute: 2 k-slices of 8
        #pragma unroll
        for (int ks = 0; ks < 2; ks++) {
            const int kb = ks * 8;
            uint32_t af[4][4], bf[4][2];
            #pragma unroll
            for (int i = 0; i < 4; i++) {
                const uint32_t* p0 = &As[(wm + i*16 + g    )*LDSW + kb + tg];
                const uint32_t* p1 = &As[(wm + i*16 + g + 8)*LDSW + kb + tg];
                af[i][0] = p0[0]; af[i][2] = p0[4];
                af[i][1] = p1[0]; af[i][3] = p1[4];
            }
            #pragma unroll
            for (int j = 0; j < 4; j++) {
                const uint32_t* p = &Bs[(wn + j*8 + g)*LDSW + kb + tg];
                bf[j][0] = p[0]; bf[j][1] = p[4];
            }
            #pragma unroll
            for (int i = 0; i < 4; i++)
                #pragma unroll
                for (int j = 0; j < 4; j++) {
                    float* c = acc[i*4 + j];
                    asm volatile(
                        "mma.sync.aligned.m16n8k8.row.col.f32.tf32.tf32.f32 "
                        "{%0,%1,%2,%3}, {%4,%5,%6,%7}, {%8,%9}, {%0,%1,%2,%3};"
                        : "+f"(c[0]), "+f"(c[1]), "+f"(c[2]), "+f"(c[3])
                        : "r"(af[i][0]), "r"(af[i][1]), "r"(af[i][2]), "r"(af[i][3]),
                          "r"(bf[j][0]), "r"(bf[j][1]));
                }
        }
        __syncthreads();
    }

    // ---------------- epilogue ----------------
    #pragma unroll
    for (int i = 0; i < 4; i++) {
        #pragma unroll
        for (int j = 0; j < 4; j++) {
            int row = bm + wm + i*16 + g;
            int col = bn + wn + j*8 + (tg << 1);
            if (col >= N) continue;
            float* c = acc[i*4 + j];
            float2 v0 = make_float2(c[0], c[1]);
            float2 v1 = make_float2(c[2], c[3]);
            if (EPI == 1 || EPI == 3) {
                float2 bv = *(const float2*)&bias[col];
                v0.x += bv.x; v0.y += bv.y;
                v1.x += bv.x; v1.y += bv.y;
            }
            if (EPI == 1) {
                v0.x = geluf(v0.x); v0.y = geluf(v0.y);
                v1.x = geluf(v1.x); v1.y = geluf(v1.y);
            }
            if (EPI == 2 || EPI == 3) {
                float2 r0 = *(const float2*)&res[(size_t)row*N + col];
                float2 r1 = *(const float2*)&res[(size_t)(row+8)*N + col];
                v0.x += r0.x; v0.y += r0.y;
                v1.x += r1.x; v1.y += r1.y;
            }
            *(float2*)&C[(size_t)row*N + col]     = v0;
            *(float2*)&C[(size_t)(row+8)*N + col] = v1;
        }
    }
}

// ---------------- dt preprocess ----------------
__global__ void dt_kernel(const float* __restrict__ zx, const float* __restrict__ dt_bias,
                          const float* __restrict__ A_log,
                          float* __restrict__ dec, float* __restrict__ dts)
{
    int idx = blockIdx.x * blockDim.x + threadIdx.x;
    int hh = idx & 15;
    int t  = (idx >> 4) & (SEQLEN - 1);
    int s  = idx >> 15;
    int b  = s & 3;
    int off = (s < 4) ? 0 : NHEADSN;
    float raw = zx[((size_t)b*SEQLEN + t)*DINPROJ + (DINNER + CONVDIM) + off + hh] + dt_bias[hh];
    float sp = (raw > 20.f) ? raw : log1pf(expf(raw));
    float Ah = -expf(A_log[hh]);
    dec[idx] = expf(Ah * sp);
    dts[idx] = sp;
}

// ---------------- depthwise causal conv7 + bias + silu ----------------
__global__ void conv_kernel(const float* __restrict__ zx, const float* __restrict__ cw,
                            const float* __restrict__ cb, float* __restrict__ out)
{
    int idx = blockIdx.x * blockDim.x + threadIdx.x;
    int c  = idx % CONVDIM;
    int bt = idx / CONVDIM;
    int t  = bt & (SEQLEN - 1);
    int b  = bt >> 11;
    float acc = cb[c];
    #pragma unroll
    for (int j = 0; j < 7; j++) {
        int tt = t - 6 + j;
        if (tt >= 0)
            acc = fmaf(zx[((size_t)b*SEQLEN + tt)*DINPROJ + DINNER + c], cw[c*7 + j], acc);
    }
    out[idx] = siluf(acc);
}

// ---------------- bidirectional SSM scan ----------------
__global__ void __launch_bounds__(256) scan_kernel(
    const float* __restrict__ xbc, const float* __restrict__ dec,
    const float* __restrict__ dts, float* __restrict__ y)
{
    const int h = blockIdx.x;
    const int s = blockIdx.y;
    const int b = s & 3;
    const bool fw = (s < 4);
    const int tid = threadIdx.x;
    const int p = tid >> 2;
    const int q = tid & 3;

    __shared__ float sB[16][64], sC[16][64], sX[16][64];
    __shared__ float sDec[16], sDt[16];

    float hreg[16];
    #pragma unroll
    for (int i = 0; i < 16; i++) hreg[i] = 0.f;

    const float* base = xbc + (size_t)b*SEQLEN*CONVDIM;
    float* yout = y + (size_t)s*SEQLEN*DINNER + h*HEADDIM + p;

    if (q == 0) {
        int t0 = fw ? 0 : (SEQLEN - 1);
        yout[(size_t)t0*DINNER] = 0.f;
    }

    for (int cc = 0; cc < SEQLEN/16; cc++) {
        for (int i = tid; i < 16*64; i += 256) {
            int j = i >> 6, n = i & 63;
            int tau = cc*16 + j;
            int orig = fw ? tau : (SEQLEN - 1 - tau);
            const float* row = base + (size_t)orig*CONVDIM;
            sX[j][n] = row[h*HEADDIM + n];
            sB[j][n] = row[DINNER + n];
            sC[j][n] = row[DINNER + DSTATE + n];
        }
        if (tid < 16) {
            int tau = cc*16 + tid;
            int orig = fw ? tau : (SEQLEN - 1 - tau);
            size_t di = ((size_t)s*SEQLEN + orig)*NHEADSN + h;
            sDec[tid] = dec[di];
            sDt[tid]  = dts[di];
        }
        __syncthreads();

        #pragma unroll 4
        for (int j = 0; j < 16; j++) {
            float d  = sDec[j];
            float dtv = sDt[j];
            float dtx = dtv * sX[j][p];
            const float4* B4 = (const float4*)&sB[j][q << 4];
            const float4* C4 = (const float4*)&sC[j][q << 4];
            float ysum = 0.f;
            #pragma unroll
            for (int v = 0; v < 4; v++) {
                float4 bb = B4[v], cv = C4[v];
                hreg[v*4+0] = fmaf(hreg[v*4+0], d, dtx*bb.x); ysum = fmaf(hreg[v*4+0], cv.x, ysum);
                hreg[v*4+1] = fmaf(hreg[v*4+1], d, dtx*bb.y); ysum = fmaf(hreg[v*4+1], cv.y, ysum);
                hreg[v*4+2] = fmaf(hreg[v*4+2], d, dtx*bb.z); ysum = fmaf(hreg[v*4+2], cv.z, ysum);
                hreg[v*4+3] = fmaf(hreg[v*4+3], d, dtx*bb.w); ysum = fmaf(hreg[v*4+3], cv.w, ysum);
            }
            ysum += __shfl_xor_sync(0xffffffffu, ysum, 1);
            ysum += __shfl_xor_sync(0xffffffffu, ysum, 2);
            if (q == 0) {
                int tau = cc*16 + j;
                int to = fw ? (tau + 1) : (SEQLEN - 2 - tau);
                if (to >= 0 && to < SEQLEN)
                    yout[(size_t)to*DINNER] = ysum;
            }
        }
        __syncthreads();
    }
}

// ---------------- gating + D skip + RMS norm ----------------
__global__ void __launch_bounds__(256) gate_rms_kernel(
    const float* __restrict__ y, const float* __restrict__ xbc,
    const float* __restrict__ zx, const float* __restrict__ Dp,
    const float* __restrict__ rms_w, float* __restrict__ out)
{
    int row = blockIdx.x;
    int b = row >> 11, t = row & 2047;
    int c = threadIdx.x << 2;
    size_t ybase = ((size_t)b*SEQLEN + t)*DINNER + c;
    const float4 yf = *(const float4*)&y[ybase];
    const float4 yb = *(const float4*)&y[ybase + (size_t)4*SEQLEN*DINNER];
    const float4 xo = *(const float4*)&xbc[((size_t)b*SEQLEN + t)*CONVDIM + c];
    const float4 zv = *(const float4*)&zx[((size_t)b*SEQLEN + t)*DINPROJ + c];
    float dp = Dp[c >> 6];
    float g0 = (yf.x + yb.x + xo.x*dp) * siluf(zv.x);
    float g1 = (yf.y + yb.y + xo.y*dp) * siluf(zv.y);
    float g2 = (yf.z + yb.z + xo.z*dp) * siluf(zv.z);
    float g3 = (yf.w + yb.w + xo.w*dp) * siluf(zv.w);
    float ss = g0*g0 + g1*g1 + g2*g2 + g3*g3;
    #pragma unroll
    for (int o = 16; o > 0; o >>= 1)
        ss += __shfl_xor_sync(0xffffffffu, ss, o);
    __shared__ float asum[8];
    int wid = threadIdx.x >> 5;
    if ((threadIdx.x & 31) == 0) asum[wid] = ss;
    __syncthreads();
    ss = asum[0]+asum[1]+asum[2]+asum[3]+asum[4]+asum[5]+asum[6]+asum[7];
    float scale = rsqrtf(ss * (1.0f/DINNER) + EPSV);
    const float4 wv = *(const float4*)&rms_w[c];
    float4 o;
    o.x = g0*scale*wv.x; o.y = g1*scale*wv.y;
    o.z = g2*scale*wv.z; o.w = g3*scale*wv.w;
    *(float4*)&out[(size_t)row*DINNER + c] = o;
}

// ---------------- launcher ----------------
extern "C" void kernel_launch(void* const* d_in, const int* in_sizes, int n_in,
                              void* d_out, int out_size)
{
    const float* x         = (const float*)d_in[0];
    const float* ln1_w     = (const float*)d_in[1];
    const float* ln1_b     = (const float*)d_in[2];
    const float* in_proj_w = (const float*)d_in[3];
    const float* conv_w    = (const float*)d_in[4];
    const float* conv_b    = (const float*)d_in[5];
    const float* dt_bias   = (const float*)d_in[6];
    const float* A_log     = (const float*)d_in[7];
    const float* Dp        = (const float*)d_in[8];
    const float* rms_w     = (const float*)d_in[9];
    const float* out_proj_w= (const float*)d_in[10];
    const float* ln2_w     = (const float*)d_in[11];
    const float* ln2_b     = (const float*)d_in[12];
    const float* fc1_w     = (const float*)d_in[13];
    const float* fc1_b     = (const float*)d_in[14];
    const float* fc2_w     = (const float*)d_in[15];
    const float* fc2_b     = (const float*)d_in[16];
    float* out = (float*)d_out;

    float *h, *zx, *xbc, *dec, *dts, *y, *yg, *x2, *ff1;
    cudaGetSymbolAddress((void**)&h,   g_h);
    cudaGetSymbolAddress((void**)&zx,  g_zx);
    cudaGetSymbolAddress((void**)&xbc, g_xbc);
    cudaGetSymbolAddress((void**)&dec, g_dec);
    cudaGetSymbolAddress((void**)&dts, g_dts);
    cudaGetSymbolAddress((void**)&y,   g_y);
    cudaGetSymbolAddress((void**)&yg,  g_yg);
    cudaGetSymbolAddress((void**)&x2,  g_x2);
    cudaGetSymbolAddress((void**)&ff1, g_ff1);

    // 1. LN1
    ln_kernel<<<NROWS, 128>>>(x, ln1_w, ln1_b, h);
    // 2. in_proj: [8192,512] @ [2208,512]^T
    gemm_tc<0><<<dim3((DINPROJ + 127)/128, NROWS/128), 256>>>(
        h, in_proj_w, nullptr, nullptr, zx, NROWS, DINPROJ, DMODEL);
    // 3. dt preprocess
    dt_kernel<<<(8*SEQLEN*NHEADSN)/256, 256>>>(zx, dt_bias, A_log, dec, dts);
    // 4. conv + silu
    conv_kernel<<<(NROWS*CONVDIM)/256, 256>>>(zx, conv_w, conv_b, xbc);
    // 5. bidirectional SSM scan
    scan_kernel<<<dim3(NHEADSN, 8), 256>>>(xbc, dec, dts, y);
    // 6. gate + D skip + RMS norm
    gate_rms_kernel<<<NROWS, 256>>>(y, xbc, zx, Dp, rms_w, yg);
    // 7. out_proj + residual(x): [8192,1024] @ [512,1024]^T
    gemm_tc<2><<<dim3(DMODEL/128, NROWS/128), 256>>>(
        yg, out_proj_w, nullptr, x, x2, NROWS, DMODEL, DINNER);
    // 8. LN2
    ln_kernel<<<NROWS, 128>>>(x2, ln2_w, ln2_b, h);
    // 9. fc1 + bias + gelu: [8192,512] @ [2048,512]^T
    gemm_tc<1><<<dim3(DFF/128, NROWS/128), 256>>>(
        h, fc1_w, fc1_b, nullptr, ff1, NROWS, DFF, DMODEL);
    // 10. fc2 + bias + residual(x2): [8192,2048] @ [512,2048]^T -> d_out
    gemm_tc<3><<<dim3(DMODEL/128, NROWS/128), 256>>>(
        ff1, fc2_w, fc2_b, x2, out, NROWS, DMODEL, DFF);
}

// round 3
// speedup vs baseline: 1.6946x; 1.0760x over previous
#include <cuda_runtime.h>
#include <math.h>
#include <stdint.h>

// ---------------- problem constants ----------------
#define BATCHN  4
#define SEQLEN  2048
#define DMODEL  512
#define DINNER  1024
#define NHEADSN 16
#define HEADDIM 64
#define DSTATE  64
#define CONVDIM 1152
#define DINPROJ 2208
#define DFF     2048
#define NROWS   (BATCHN*SEQLEN)   // 8192
#define EPSV    1e-5f

// ---------------- scratch (device globals; no allocation allowed) ----------------
__device__ float g_h   [NROWS*DMODEL];
__device__ float g_zx  [NROWS*DINPROJ];
__device__ float g_xbc [NROWS*CONVDIM];
__device__ float g_dec [8*SEQLEN*NHEADSN];
__device__ float g_dts [8*SEQLEN*NHEADSN];
__device__ float g_y   [8*SEQLEN*DINNER];
__device__ float g_yg  [NROWS*DINNER];
__device__ float g_x2  [NROWS*DMODEL];
__device__ float g_ff1 [NROWS*DFF];

// ---------------- helpers ----------------
__device__ __forceinline__ float geluf(float x) {
    return 0.5f * x * (1.0f + erff(x * 0.70710678118654752f));
}
__device__ __forceinline__ float siluf(float x) {
    return x / (1.0f + expf(-x));
}
__device__ __forceinline__ uint32_t sptr(const void* p) {
    return (uint32_t)__cvta_generic_to_shared(p);
}
// round-to-nearest tf32 prep: add half-ulp of the 13-bit truncation the HW does
__device__ __forceinline__ uint32_t rn13(uint32_t x) { return x + 0x1000u; }

#define CP16(dst, src) \
    asm volatile("cp.async.cg.shared.global [%0], [%1], 16;" :: "r"(dst), "l"(src))
#define CP16Z(dst, src, sz) \
    asm volatile("cp.async.cg.shared.global [%0], [%1], 16, %2;" :: "r"(dst), "l"(src), "r"(sz))
#define CP_COMMIT() asm volatile("cp.async.commit_group;")
#define CP_WAIT1()  asm volatile("cp.async.wait_group 1;")

// ---------------- LayerNorm (D=512) ----------------
__global__ void __launch_bounds__(128) ln_kernel(
    const float* __restrict__ x, const float* __restrict__ w,
    const float* __restrict__ b, float* __restrict__ out)
{
    int row = blockIdx.x;
    int tid = threadIdx.x;
    const float4 v = ((const float4*)(x + (size_t)row*DMODEL))[tid];
    float s  = v.x + v.y + v.z + v.w;
    float ss = v.x*v.x + v.y*v.y + v.z*v.z + v.w*v.w;
    #pragma unroll
    for (int o = 16; o > 0; o >>= 1) {
        s  += __shfl_xor_sync(0xffffffffu, s,  o);
        ss += __shfl_xor_sync(0xffffffffu, ss, o);
    }
    __shared__ float as[4], ass[4];
    int wid = tid >> 5;
    if ((tid & 31) == 0) { as[wid] = s; ass[wid] = ss; }
    __syncthreads();
    s  = as[0] + as[1] + as[2] + as[3];
    ss = ass[0] + ass[1] + ass[2] + ass[3];
    float mean = s * (1.0f/DMODEL);
    float var  = ss * (1.0f/DMODEL) - mean*mean;
    float rstd = rsqrtf(var + EPSV);
    const float4 wv = ((const float4*)w)[tid];
    const float4 bv = ((const float4*)b)[tid];
    float4 o;
    o.x = (v.x - mean)*rstd*wv.x + bv.x;
    o.y = (v.y - mean)*rstd*wv.y + bv.y;
    o.z = (v.z - mean)*rstd*wv.z + bv.z;
    o.w = (v.w - mean)*rstd*wv.w + bv.w;
    ((float4*)(out + (size_t)row*DMODEL))[tid] = o;
}

// ---------------- TF32 tensor-core GEMM, 3-stage cp.async pipeline ----------------
// C[M,N] = A[M,K] @ W[N,K]^T (+epilogue)
// EPI: 0 = none, 1 = +bias,gelu, 2 = +res, 3 = +bias +res
// Block 128x128x16, 8 warps each 64x32, mma.m16n8k8.tf32.
#define GSTAGES 3
#define GLDSW   20              // 16 + 4 pad words; row = 80B (16B aligned)
#define GSMEM_WORDS (GSTAGES * 128 * GLDSW)          // per operand
#define GSMEM_BYTES (GSMEM_WORDS * 2 * 4)            // A + B

template<int EPI>
__global__ void __launch_bounds__(256) gemm_tc(
    const float* __restrict__ A, const float* __restrict__ W,
    const float* __restrict__ bias, const float* __restrict__ res,
    float* __restrict__ C, int M, int N, int K)
{
    extern __shared__ uint32_t gsm[];
    uint32_t* As = gsm;
    uint32_t* Bs = gsm + GSMEM_WORDS;

    const int tid  = threadIdx.x;
    const int wid  = tid >> 5, lane = tid & 31;
    const int wm   = (wid >> 2) << 6;     // 0 / 64
    const int wn   = (wid & 3)  << 5;     // 0,32,64,96
    const int g    = lane >> 2, tg = lane & 3;
    const int bm   = blockIdx.y << 7, bn = blockIdx.x << 7;

    const int ldr = tid >> 2;             // 0..63
    const int ldc = (tid & 3) << 2;       // 0,4,8,12
    const int n0g = bn + ldr, n1g = bn + ldr + 64;
    const int n0c = (n0g < N) ? n0g : (N - 1);
    const int n1c = (n1g < N) ? n1g : (N - 1);
    const uint32_t bsz0 = (n0g < N) ? 16u : 0u;
    const uint32_t bsz1 = (n1g < N) ? 16u : 0u;

    // smem dst addresses for this thread's 4 cp.async chunks (per stage)
    const uint32_t dA0 = sptr(&As[ldr*GLDSW + ldc]);
    const uint32_t dA1 = dA0 + 64*GLDSW*4;
    const uint32_t dB0 = sptr(&Bs[ldr*GLDSW + ldc]);
    const uint32_t dB1 = dB0 + 64*GLDSW*4;
    const uint32_t stageB = 128*GLDSW*4;

    const float* sa0 = A + (size_t)(bm + ldr)*K + ldc;
    const float* sa1 = sa0 + (size_t)64*K;
    const float* sb0 = W + (size_t)n0c*K + ldc;
    const float* sb1 = W + (size_t)n1c*K + ldc;

    const int ntiles = K >> 4;

    // prologue: stages 0..GSTAGES-2
    #pragma unroll
    for (int s = 0; s < GSTAGES-1; s++) {
        int k0 = s << 4;
        CP16 (dA0 + s*stageB, sa0 + k0);
        CP16 (dA1 + s*stageB, sa1 + k0);
        CP16Z(dB0 + s*stageB, sb0 + k0, bsz0);
        CP16Z(dB1 + s*stageB, sb1 + k0, bsz1);
        CP_COMMIT();
    }

    float acc[16][4];
    #pragma unroll
    for (int i = 0; i < 16; i++) { acc[i][0]=acc[i][1]=acc[i][2]=acc[i][3]=0.f; }

    for (int t = 0; t < ntiles; t++) {
        CP_WAIT1();
        __syncthreads();

        // issue load for tile t+GSTAGES-1 into stage (t+GSTAGES-1)%GSTAGES
        int tf = t + GSTAGES - 1;
        if (tf < ntiles) {
            int st = tf % GSTAGES;
            int k0 = tf << 4;
            CP16 (dA0 + st*stageB, sa0 + k0);
            CP16 (dA1 + st*stageB, sa1 + k0);
            CP16Z(dB0 + st*stageB, sb0 + k0, bsz0);
            CP16Z(dB1 + st*stageB, sb1 + k0, bsz1);
        }
        CP_COMMIT();

        const uint32_t* Ast = As + (t % GSTAGES)*128*GLDSW;
        const uint32_t* Bst = Bs + (t % GSTAGES)*128*GLDSW;

        #pragma unroll
        for (int ks = 0; ks < 2; ks++) {
            const int kb = ks * 8;
            uint32_t af[4][4], bf[4][2];
            #pragma unroll
            for (int i = 0; i < 4; i++) {
                const uint32_t* p0 = &Ast[(wm + i*16 + g    )*GLDSW + kb + tg];
                const uint32_t* p1 = &Ast[(wm + i*16 + g + 8)*GLDSW + kb + tg];
                af[i][0] = rn13(p0[0]); af[i][2] = rn13(p0[4]);
                af[i][1] = rn13(p1[0]); af[i][3] = rn13(p1[4]);
            }
            #pragma unroll
            for (int j = 0; j < 4; j++) {
                const uint32_t* p = &Bst[(wn + j*8 + g)*GLDSW + kb + tg];
                bf[j][0] = rn13(p[0]); bf[j][1] = rn13(p[4]);
            }
            #pragma unroll
            for (int i = 0; i < 4; i++)
                #pragma unroll
                for (int j = 0; j < 4; j++) {
                    float* c = acc[i*4 + j];
                    asm volatile(
                        "mma.sync.aligned.m16n8k8.row.col.f32.tf32.tf32.f32 "
                        "{%0,%1,%2,%3}, {%4,%5,%6,%7}, {%8,%9}, {%0,%1,%2,%3};"
                        : "+f"(c[0]), "+f"(c[1]), "+f"(c[2]), "+f"(c[3])
                        : "r"(af[i][0]), "r"(af[i][1]), "r"(af[i][2]), "r"(af[i][3]),
                          "r"(bf[j][0]), "r"(bf[j][1]));
                }
        }
    }

    // ---------------- epilogue ----------------
    #pragma unroll
    for (int i = 0; i < 4; i++) {
        #pragma unroll
        for (int j = 0; j < 4; j++) {
            int row = bm + wm + i*16 + g;
            int col = bn + wn + j*8 + (tg << 1);
            if (col >= N) continue;
            float* c = acc[i*4 + j];
            float2 v0 = make_float2(c[0], c[1]);
            float2 v1 = make_float2(c[2], c[3]);
            if (EPI == 1 || EPI == 3) {
                float2 bv = *(const float2*)&bias[col];
                v0.x += bv.x; v0.y += bv.y;
                v1.x += bv.x; v1.y += bv.y;
            }
            if (EPI == 1) {
                v0.x = geluf(v0.x); v0.y = geluf(v0.y);
                v1.x = geluf(v1.x); v1.y = geluf(v1.y);
            }
            if (EPI == 2 || EPI == 3) {
                float2 r0 = *(const float2*)&res[(size_t)row*N + col];
                float2 r1 = *(const float2*)&res[(size_t)(row+8)*N + col];
                v0.x += r0.x; v0.y += r0.y;
                v1.x += r1.x; v1.y += r1.y;
            }
            *(float2*)&C[(size_t)row*N + col]     = v0;
            *(float2*)&C[(size_t)(row+8)*N + col] = v1;
        }
    }
}

// ---------------- dt preprocess ----------------
__global__ void dt_kernel(const float* __restrict__ zx, const float* __restrict__ dt_bias,
                          const float* __restrict__ A_log,
                          float* __restrict__ dec, float* __restrict__ dts)
{
    int idx = blockIdx.x * blockDim.x + threadIdx.x;
    int hh = idx & 15;
    int t  = (idx >> 4) & (SEQLEN - 1);
    int s  = idx >> 15;
    int b  = s & 3;
    int off = (s < 4) ? 0 : NHEADSN;
    float raw = zx[((size_t)b*SEQLEN + t)*DINPROJ + (DINNER + CONVDIM) + off + hh] + dt_bias[hh];
    float sp = (raw > 20.f) ? raw : log1pf(expf(raw));
    float Ah = -expf(A_log[hh]);
    dec[idx] = expf(Ah * sp);
    dts[idx] = sp;
}

// ---------------- depthwise causal conv7 + bias + silu ----------------
__global__ void conv_kernel(const float* __restrict__ zx, const float* __restrict__ cw,
                            const float* __restrict__ cb, float* __restrict__ out)
{
    int idx = blockIdx.x * blockDim.x + threadIdx.x;
    int c  = idx % CONVDIM;
    int bt = idx / CONVDIM;
    int t  = bt & (SEQLEN - 1);
    int b  = bt >> 11;
    float acc = cb[c];
    #pragma unroll
    for (int j = 0; j < 7; j++) {
        int tt = t - 6 + j;
        if (tt >= 0)
            acc = fmaf(zx[((size_t)b*SEQLEN + tt)*DINPROJ + DINNER + c], cw[c*7 + j], acc);
    }
    out[idx] = siluf(acc);
}

// ---------------- bidirectional SSM scan ----------------
__global__ void __launch_bounds__(256) scan_kernel(
    const float* __restrict__ xbc, const float* __restrict__ dec,
    const float* __restrict__ dts, float* __restrict__ y)
{
    const int h = blockIdx.x;
    const int s = blockIdx.y;
    const int b = s & 3;
    const bool fw = (s < 4);
    const int tid = threadIdx.x;
    const int p = tid >> 2;
    const int q = tid & 3;

    __shared__ float sB[16][64], sC[16][64], sX[16][64];
    __shared__ float sDec[16], sDt[16];

    float hreg[16];
    #pragma unroll
    for (int i = 0; i < 16; i++) hreg[i] = 0.f;

    const float* base = xbc + (size_t)b*SEQLEN*CONVDIM;
    float* yout = y + (size_t)s*SEQLEN*DINNER + h*HEADDIM + p;

    if (q == 0) {
        int t0 = fw ? 0 : (SEQLEN - 1);
        yout[(size_t)t0*DINNER] = 0.f;
    }

    for (int cc = 0; cc < SEQLEN/16; cc++) {
        for (int i = tid; i < 16*64; i += 256) {
            int j = i >> 6, n = i & 63;
            int tau = cc*16 + j;
            int orig = fw ? tau : (SEQLEN - 1 - tau);
            const float* row = base + (size_t)orig*CONVDIM;
            sX[j][n] = row[h*HEADDIM + n];
            sB[j][n] = row[DINNER + n];
            sC[j][n] = row[DINNER + DSTATE + n];
        }
        if (tid < 16) {
            int tau = cc*16 + tid;
            int orig = fw ? tau : (SEQLEN - 1 - tau);
            size_t di = ((size_t)s*SEQLEN + orig)*NHEADSN + h;
            sDec[tid] = dec[di];
            sDt[tid]  = dts[di];
        }
        __syncthreads();

        #pragma unroll 4
        for (int j = 0; j < 16; j++) {
            float d  = sDec[j];
            float dtv = sDt[j];
            float dtx = dtv * sX[j][p];
            const float4* B4 = (const float4*)&sB[j][q << 4];
            const float4* C4 = (const float4*)&sC[j][q << 4];
            float ysum = 0.f;
            #pragma unroll
            for (int v = 0; v < 4; v++) {
                float4 bb = B4[v], cv = C4[v];
                hreg[v*4+0] = fmaf(hreg[v*4+0], d, dtx*bb.x); ysum = fmaf(hreg[v*4+0], cv.x, ysum);
                hreg[v*4+1] = fmaf(hreg[v*4+1], d, dtx*bb.y); ysum = fmaf(hreg[v*4+1], cv.y, ysum);
                hreg[v*4+2] = fmaf(hreg[v*4+2], d, dtx*bb.z); ysum = fmaf(hreg[v*4+2], cv.z, ysum);
                hreg[v*4+3] = fmaf(hreg[v*4+3], d, dtx*bb.w); ysum = fmaf(hreg[v*4+3], cv.w, ysum);
            }
            ysum += __shfl_xor_sync(0xffffffffu, ysum, 1);
            ysum += __shfl_xor_sync(0xffffffffu, ysum, 2);
            if (q == 0) {
                int tau = cc*16 + j;
                int to = fw ? (tau + 1) : (SEQLEN - 2 - tau);
                if (to >= 0 && to < SEQLEN)
                    yout[(size_t)to*DINNER] = ysum;
            }
        }
        __syncthreads();
    }
}

// ---------------- gating + D skip + RMS norm ----------------
__global__ void __launch_bounds__(256) gate_rms_kernel(
    const float* __restrict__ y, const float* __restrict__ xbc,
    const float* __restrict__ zx, const float* __restrict__ Dp,
    const float* __restrict__ rms_w, float* __restrict__ out)
{
    int row = blockIdx.x;
    int b = row >> 11, t = row & 2047;
    int c = threadIdx.x << 2;
    size_t ybase = ((size_t)b*SEQLEN + t)*DINNER + c;
    const float4 yf = *(const float4*)&y[ybase];
    const float4 yb = *(const float4*)&y[ybase + (size_t)4*SEQLEN*DINNER];
    const float4 xo = *(const float4*)&xbc[((size_t)b*SEQLEN + t)*CONVDIM + c];
    const float4 zv = *(const float4*)&zx[((size_t)b*SEQLEN + t)*DINPROJ + c];
    float dp = Dp[c >> 6];
    float g0 = (yf.x + yb.x + xo.x*dp) * siluf(zv.x);
    float g1 = (yf.y + yb.y + xo.y*dp) * siluf(zv.y);
    float g2 = (yf.z + yb.z + xo.z*dp) * siluf(zv.z);
    float g3 = (yf.w + yb.w + xo.w*dp) * siluf(zv.w);
    float ss = g0*g0 + g1*g1 + g2*g2 + g3*g3;
    #pragma unroll
    for (int o = 16; o > 0; o >>= 1)
        ss += __shfl_xor_sync(0xffffffffu, ss, o);
    __shared__ float asum[8];
    int wid = threadIdx.x >> 5;
    if ((threadIdx.x & 31) == 0) asum[wid] = ss;
    __syncthreads();
    ss = asum[0]+asum[1]+asum[2]+asum[3]+asum[4]+asum[5]+asum[6]+asum[7];
    float scale = rsqrtf(ss * (1.0f/DINNER) + EPSV);
    const float4 wv = *(const float4*)&rms_w[c];
    float4 o;
    o.x = g0*scale*wv.x; o.y = g1*scale*wv.y;
    o.z = g2*scale*wv.z; o.w = g3*scale*wv.w;
    *(float4*)&out[(size_t)row*DINNER + c] = o;
}

// ---------------- launcher ----------------
extern "C" void kernel_launch(void* const* d_in, const int* in_sizes, int n_in,
                              void* d_out, int out_size)
{
    const float* x         = (const float*)d_in[0];
    const float* ln1_w     = (const float*)d_in[1];
    const float* ln1_b     = (const float*)d_in[2];
    const float* in_proj_w = (const float*)d_in[3];
    const float* conv_w    = (const float*)d_in[4];
    const float* conv_b    = (const float*)d_in[5];
    const float* dt_bias   = (const float*)d_in[6];
    const float* A_log     = (const float*)d_in[7];
    const float* Dp        = (const float*)d_in[8];
    const float* rms_w     = (const float*)d_in[9];
    const float* out_proj_w= (const float*)d_in[10];
    const float* ln2_w     = (const float*)d_in[11];
    const float* ln2_b     = (const float*)d_in[12];
    const float* fc1_w     = (const float*)d_in[13];
    const float* fc1_b     = (const float*)d_in[14];
    const float* fc2_w     = (const float*)d_in[15];
    const float* fc2_b     = (const float*)d_in[16];
    float* out = (float*)d_out;

    float *h, *zx, *xbc, *dec, *dts, *y, *yg, *x2, *ff1;
    cudaGetSymbolAddress((void**)&h,   g_h);
    cudaGetSymbolAddress((void**)&zx,  g_zx);
    cudaGetSymbolAddress((void**)&xbc, g_xbc);
    cudaGetSymbolAddress((void**)&dec, g_dec);
    cudaGetSymbolAddress((void**)&dts, g_dts);
    cudaGetSymbolAddress((void**)&y,   g_y);
    cudaGetSymbolAddress((void**)&yg,  g_yg);
    cudaGetSymbolAddress((void**)&x2,  g_x2);
    cudaGetSymbolAddress((void**)&ff1, g_ff1);

    static bool attr_done = false;
    if (!attr_done) {
        cudaFuncSetAttribute(gemm_tc<0>, cudaFuncAttributeMaxDynamicSharedMemorySize, GSMEM_BYTES);
        cudaFuncSetAttribute(gemm_tc<1>, cudaFuncAttributeMaxDynamicSharedMemorySize, GSMEM_BYTES);
        cudaFuncSetAttribute(gemm_tc<2>, cudaFuncAttributeMaxDynamicSharedMemorySize, GSMEM_BYTES);
        cudaFuncSetAttribute(gemm_tc<3>, cudaFuncAttributeMaxDynamicSharedMemorySize, GSMEM_BYTES);
        attr_done = true;
    }

    // 1. LN1
    ln_kernel<<<NROWS, 128>>>(x, ln1_w, ln1_b, h);
    // 2. in_proj: [8192,512] @ [2208,512]^T
    gemm_tc<0><<<dim3((DINPROJ + 127)/128, NROWS/128), 256, GSMEM_BYTES>>>(
        h, in_proj_w, nullptr, nullptr, zx, NROWS, DINPROJ, DMODEL);
    // 3. dt preprocess
    dt_kernel<<<(8*SEQLEN*NHEADSN)/256, 256>>>(zx, dt_bias, A_log, dec, dts);
    // 4. conv + silu
    conv_kernel<<<(NROWS*CONVDIM)/256, 256>>>(zx, conv_w, conv_b, xbc);
    // 5. bidirectional SSM scan
    scan_kernel<<<dim3(NHEADSN, 8), 256>>>(xbc, dec, dts, y);
    // 6. gate + D skip + RMS norm
    gate_rms_kernel<<<NROWS, 256>>>(y, xbc, zx, Dp, rms_w, yg);
    // 7. out_proj + residual(x): [8192,1024] @ [512,1024]^T
    gemm_tc<2><<<dim3(DMODEL/128, NROWS/128), 256, GSMEM_BYTES>>>(
        yg, out_proj_w, nullptr, x, x2, NROWS, DMODEL, DINNER);
    // 8. LN2
    ln_kernel<<<NROWS, 128>>>(x2, ln2_w, ln2_b, h);
    // 9. fc1 + bias + gelu: [8192,512] @ [2048,512]^T
    gemm_tc<1><<<dim3(DFF/128, NROWS/128), 256, GSMEM_BYTES>>>(
        h, fc1_w, fc1_b, nullptr, ff1, NROWS, DFF, DMODEL);
    // 10. fc2 + bias + residual(x2): [8192,2048] @ [512,2048]^T -> d_out
    gemm_tc<3><<<dim3(DMODEL/128, NROWS/128), 256, GSMEM_BYTES>>>(
        ff1, fc2_w, fc2_b, x2, out, NROWS, DMODEL, DFF);
}

// round 5
// speedup vs baseline: 2.0195x; 1.1917x over previous
#include <cuda_runtime.h>
#include <cuda_fp16.h>
#include <math.h>
#include <stdint.h>

// ---------------- problem constants ----------------
#define BATCHN  4
#define SEQLEN  2048
#define DMODEL  512
#define DINNER  1024
#define NHEADSN 16
#define HEADDIM 64
#define DSTATE  64
#define CONVDIM 1152
#define DINPROJ 2208
#define DFF     2048
#define NROWS   (BATCHN*SEQLEN)   // 8192
#define EPSV    1e-5f

// ---------------- scratch (device globals; no allocation allowed) ----------------
__device__ float  g_zx  [NROWS*DINPROJ];
__device__ float  g_xbc [NROWS*CONVDIM];
__device__ float  g_dec [8*SEQLEN*NHEADSN];
__device__ float  g_dts [8*SEQLEN*NHEADSN];
__device__ float  g_y   [8*SEQLEN*DINNER];
__device__ float  g_x2  [NROWS*DMODEL];
__device__ __half g_h16 [NROWS*DMODEL];     // LN output (fp16, GEMM A)
__device__ __half g_yg16[NROWS*DINNER];     // gated+rms (fp16, GEMM A)
__device__ __half g_ff1h[NROWS*DFF];        // gelu(fc1) (fp16, GEMM A)
__device__ __half g_wip [DINPROJ*DMODEL];   // fp16 weights
__device__ __half g_wop [DMODEL*DINNER];
__device__ __half g_w1  [DFF*DMODEL];
__device__ __half g_w2  [DMODEL*DFF];

// ---------------- helpers ----------------
__device__ __forceinline__ float geluf(float x) {
    return 0.5f * x * (1.0f + erff(x * 0.70710678118654752f));
}
__device__ __forceinline__ float siluf(float x) {
    return x / (1.0f + expf(-x));
}

#define CP16(dst, src) \
    asm volatile("cp.async.cg.shared.global [%0], [%1], 16;" :: "r"(dst), "l"(src))
#define CP16Z(dst, src, sz) \
    asm volatile("cp.async.cg.shared.global [%0], [%1], 16, %2;" :: "r"(dst), "l"(src), "r"(sz))
#define CP_COMMIT() asm volatile("cp.async.commit_group;")
#define CP_WAIT2()  asm volatile("cp.async.wait_group 2;")

__device__ __forceinline__ void ldsm4(uint32_t& q0, uint32_t& q1, uint32_t& q2, uint32_t& q3,
                                      uint32_t addr) {
    asm volatile("ldmatrix.sync.aligned.m8n8.x4.shared.b16 {%0,%1,%2,%3}, [%4];"
        : "=r"(q0), "=r"(q1), "=r"(q2), "=r"(q3) : "r"(addr));
}

// ---------------- f32 -> f16 convert ----------------
__global__ void cvt_kernel(const float* __restrict__ src, __half* __restrict__ dst, int n)
{
    int i = (blockIdx.x*blockDim.x + threadIdx.x) << 2;
    if (i >= n) return;
    float4 v = *(const float4*)&src[i];
    *(__half2*)&dst[i]   = __floats2half2_rn(v.x, v.y);
    *(__half2*)&dst[i+2] = __floats2half2_rn(v.z, v.w);
}

// ---------------- LayerNorm (D=512), fp16 output ----------------
__global__ void __launch_bounds__(128) ln_kernel(
    const float* __restrict__ x, const float* __restrict__ w,
    const float* __restrict__ b, __half* __restrict__ out)
{
    int row = blockIdx.x;
    int tid = threadIdx.x;
    const float4 v = ((const float4*)(x + (size_t)row*DMODEL))[tid];
    float s  = v.x + v.y + v.z + v.w;
    float ss = v.x*v.x + v.y*v.y + v.z*v.z + v.w*v.w;
    #pragma unroll
    for (int o = 16; o > 0; o >>= 1) {
        s  += __shfl_xor_sync(0xffffffffu, s,  o);
        ss += __shfl_xor_sync(0xffffffffu, ss, o);
    }
    __shared__ float as[4], ass[4];
    int wid = tid >> 5;
    if ((tid & 31) == 0) { as[wid] = s; ass[wid] = ss; }
    __syncthreads();
    s  = as[0] + as[1] + as[2] + as[3];
    ss = ass[0] + ass[1] + ass[2] + ass[3];
    float mean = s * (1.0f/DMODEL);
    float var  = ss * (1.0f/DMODEL) - mean*mean;
    float rstd = rsqrtf(var + EPSV);
    const float4 wv = ((const float4*)w)[tid];
    const float4 bv = ((const float4*)b)[tid];
    float o0 = (v.x - mean)*rstd*wv.x + bv.x;
    float o1 = (v.y - mean)*rstd*wv.y + bv.y;
    float o2 = (v.z - mean)*rstd*wv.z + bv.z;
    float o3 = (v.w - mean)*rstd*wv.w + bv.w;
    __half2* op = (__half2*)(out + (size_t)row*DMODEL + (tid << 2));
    op[0] = __floats2half2_rn(o0, o1);
    op[1] = __floats2half2_rn(o2, o3);
}

// ---------------- fp16 tensor-core GEMM: C[M,N] = A[M,K] @ W[N,K]^T (+epilogue) ----------------
// EPI: 0 = none, 1 = +bias,gelu, 2 = +res, 3 = +bias +res. OUTH: 1 = fp16 output.
// Block 128x128, BK=32 halves, 4-stage cp.async, 8 warps each 64x32, mma.m16n8k16.f16.
#define NSTAGE  4
#define ROWB    80                  // 32 halves + 8 pad = 80 bytes/row
#define OPSTAGE (128*ROWB)          // 10240 B per operand per stage
#define SMBOFF  (NSTAGE*OPSTAGE)    // 40960
#define GEMM_SMEM (2*NSTAGE*OPSTAGE) // 81920

template<int EPI, int OUTH>
__global__ void __launch_bounds__(256) gemm_h(
    const __half* __restrict__ A, const __half* __restrict__ W,
    const float* __restrict__ bias, const float* __restrict__ res,
    void* __restrict__ Cout, int M, int N, int K)
{
    extern __shared__ char smem[];
    const uint32_t su = (uint32_t)__cvta_generic_to_shared(smem);
    const int tid = threadIdx.x, lane = tid & 31, wid = tid >> 5;
    const int bm = blockIdx.y << 7, bn = blockIdx.x << 7;
    const int wm = (wid >> 2) << 6;     // 0 / 64
    const int wn = (wid & 3)  << 5;     // 0,32,64,96
    const int ntiles = K >> 5;

    // cp.async geometry: chunk c in {tid, tid+256}: row = c>>2 (0..127), cpos = c&3
    const int lrow = tid >> 2;          // 0..63 (second chunk: +64)
    const int lcp  = tid & 3;
    const int an0 = bn + lrow, an1 = bn + lrow + 64;
    const uint32_t bsz0 = (an0 < N) ? 16u : 0u;
    const uint32_t bsz1 = (an1 < N) ? 16u : 0u;
    const __half* aSrc0 = A + (size_t)(bm + lrow)*K + (lcp << 3);
    const __half* aSrc1 = aSrc0 + (size_t)64*K;
    const __half* bSrc0 = W + (size_t)((an0 < N) ? an0 : 0)*K + (lcp << 3);
    const __half* bSrc1 = W + (size_t)((an1 < N) ? an1 : 0)*K + (lcp << 3);
    const uint32_t dA0 = su + lrow*ROWB + (lcp << 4);
    const uint32_t dA1 = dA0 + 64*ROWB;
    const uint32_t dB0 = su + SMBOFF + lrow*ROWB + (lcp << 4);
    const uint32_t dB1 = dB0 + 64*ROWB;

    // ldmatrix lane addressing
    const int arow = ((lane >> 3) & 1)*8 + (lane & 7);
    const int abyt = (lane >> 4) << 4;
    uint32_t abase[4];
    #pragma unroll
    for (int i = 0; i < 4; i++)
        abase[i] = su + (wm + i*16 + arow)*ROWB + abyt;
    const int brow = (lane >> 4)*8 + (lane & 7);
    const int bbyt = ((lane >> 3) & 1) << 4;
    uint32_t bbase[2];
    #pragma unroll
    for (int j2 = 0; j2 < 2; j2++)
        bbase[j2] = su + SMBOFF + (wn + j2*16 + brow)*ROWB + bbyt;

    float acc[16][4];
    #pragma unroll
    for (int i = 0; i < 16; i++) { acc[i][0]=acc[i][1]=acc[i][2]=acc[i][3]=0.f; }

    auto issue_tile = [&](int tf) {
        const int st = tf & (NSTAGE-1);
        const uint32_t so = st*OPSTAGE;
        const int kh = tf << 5;                 // k offset in halves
        CP16 (dA0 + so, aSrc0 + kh);
        CP16 (dA1 + so, aSrc1 + kh);
        CP16Z(dB0 + so, bSrc0 + kh, bsz0);
        CP16Z(dB1 + so, bSrc1 + kh, bsz1);
    };

    issue_tile(0); CP_COMMIT();
    issue_tile(1); CP_COMMIT();

    for (int t = 0; t < ntiles; t++) {
        if (t + 2 < ntiles) issue_tile(t + 2);
        CP_COMMIT();
        CP_WAIT2();
        __syncthreads();

        const uint32_t so = (t & (NSTAGE-1))*OPSTAGE;
        #pragma unroll
        for (int ks = 0; ks < 2; ks++) {
            const uint32_t ko = ks << 5;        // 32B per k-step of 16 halves
            uint32_t af[4][4], bf[4][2];
            #pragma unroll
            for (int i = 0; i < 4; i++)
                ldsm4(af[i][0], af[i][1], af[i][2], af[i][3], abase[i] + so + ko);
            #pragma unroll
            for (int j2 = 0; j2 < 2; j2++) {
                uint32_t q0, q1, q2, q3;
                ldsm4(q0, q1, q2, q3, bbase[j2] + so + ko);
                bf[j2*2  ][0] = q0; bf[j2*2  ][1] = q1;
                bf[j2*2+1][0] = q2; bf[j2*2+1][1] = q3;
            }
            #pragma unroll
            for (int i = 0; i < 4; i++)
                #pragma unroll
                for (int j = 0; j < 4; j++) {
                    float* c = acc[i*4 + j];
                    asm volatile(
                        "mma.sync.aligned.m16n8k16.row.col.f32.f16.f16.f32 "
                        "{%0,%1,%2,%3}, {%4,%5,%6,%7}, {%8,%9}, {%0,%1,%2,%3};"
                        : "+f"(c[0]), "+f"(c[1]), "+f"(c[2]), "+f"(c[3])
                        : "r"(af[i][0]), "r"(af[i][1]), "r"(af[i][2]), "r"(af[i][3]),
                          "r"(bf[j][0]), "r"(bf[j][1]));
                }
        }
        __syncthreads();
    }

    // ---------------- epilogue ----------------
    const int g = lane >> 2, tg = lane & 3;
    #pragma unroll
    for (int i = 0; i < 4; i++) {
        #pragma unroll
        for (int j = 0; j < 4; j++) {
            int row = bm + wm + i*16 + g;
            int col = bn + wn + j*8 + (tg << 1);
            if (col >= N) continue;
            float* c = acc[i*4 + j];
            float2 v0 = make_float2(c[0], c[1]);
            float2 v1 = make_float2(c[2], c[3]);
            if (EPI == 1 || EPI == 3) {
                float2 bv = *(const float2*)&bias[col];
                v0.x += bv.x; v0.y += bv.y;
                v1.x += bv.x; v1.y += bv.y;
            }
            if (EPI == 1) {
                v0.x = geluf(v0.x); v0.y = geluf(v0.y);
                v1.x = geluf(v1.x); v1.y = geluf(v1.y);
            }
            if (EPI == 2 || EPI == 3) {
                float2 r0 = *(const float2*)&res[(size_t)row*N + col];
                float2 r1 = *(const float2*)&res[(size_t)(row+8)*N + col];
                v0.x += r0.x; v0.y += r0.y;
                v1.x += r1.x; v1.y += r1.y;
            }
            if (OUTH) {
                __half* Ch = (__half*)Cout;
                *(__half2*)&Ch[(size_t)row*N + col]     = __floats2half2_rn(v0.x, v0.y);
                *(__half2*)&Ch[(size_t)(row+8)*N + col] = __floats2half2_rn(v1.x, v1.y);
            } else {
                float* Cf = (float*)Cout;
                *(float2*)&Cf[(size_t)row*N + col]     = v0;
                *(float2*)&Cf[(size_t)(row+8)*N + col] = v1;
            }
        }
    }
}

// ---------------- dt preprocess ----------------
__global__ void dt_kernel(const float* __restrict__ zx, const float* __restrict__ dt_bias,
                          const float* __restrict__ A_log,
                          float* __restrict__ dec, float* __restrict__ dts)
{
    int idx = blockIdx.x * blockDim.x + threadIdx.x;
    int hh = idx & 15;
    int t  = (idx >> 4) & (SEQLEN - 1);
    int s  = idx >> 15;
    int b  = s & 3;
    int off = (s < 4) ? 0 : NHEADSN;
    float raw = zx[((size_t)b*SEQLEN + t)*DINPROJ + (DINNER + CONVDIM) + off + hh] + dt_bias[hh];
    float sp = (raw > 20.f) ? raw : log1pf(expf(raw));
    float Ah = -expf(A_log[hh]);
    dec[idx] = expf(Ah * sp);
    dts[idx] = sp;
}

// ---------------- depthwise causal conv7 + bias + silu ----------------
__global__ void conv_kernel(const float* __restrict__ zx, const float* __restrict__ cw,
                            const float* __restrict__ cb, float* __restrict__ out)
{
    int idx = blockIdx.x * blockDim.x + threadIdx.x;
    int c  = idx % CONVDIM;
    int bt = idx / CONVDIM;
    int t  = bt & (SEQLEN - 1);
    int b  = bt >> 11;
    float acc = cb[c];
    #pragma unroll
    for (int j = 0; j < 7; j++) {
        int tt = t - 6 + j;
        if (tt >= 0)
            acc = fmaf(zx[((size_t)b*SEQLEN + tt)*DINPROJ + DINNER + c], cw[c*7 + j], acc);
    }
    out[idx] = siluf(acc);
}

// ---------------- bidirectional SSM scan ----------------
__global__ void __launch_bounds__(256) scan_kernel(
    const float* __restrict__ xbc, const float* __restrict__ dec,
    const float* __restrict__ dts, float* __restrict__ y)
{
    const int h = blockIdx.x;
    const int s = blockIdx.y;
    const int b = s & 3;
    const bool fw = (s < 4);
    const int tid = threadIdx.x;
    const int p = tid >> 2;
    const int q = tid & 3;

    __shared__ float sB[16][64], sC[16][64], sX[16][64];
    __shared__ float sDec[16], sDt[16];

    float hreg[16];
    #pragma unroll
    for (int i = 0; i < 16; i++) hreg[i] = 0.f;

    const float* base = xbc + (size_t)b*SEQLEN*CONVDIM;
    float* yout = y + (size_t)s*SEQLEN*DINNER + h*HEADDIM + p;

    if (q == 0) {
        int t0 = fw ? 0 : (SEQLEN - 1);
        yout[(size_t)t0*DINNER] = 0.f;
    }

    for (int cc = 0; cc < SEQLEN/16; cc++) {
        for (int i = tid; i < 16*64; i += 256) {
            int j = i >> 6, n = i & 63;
            int tau = cc*16 + j;
            int orig = fw ? tau : (SEQLEN - 1 - tau);
            const float* row = base + (size_t)orig*CONVDIM;
            sX[j][n] = row[h*HEADDIM + n];
            sB[j][n] = row[DINNER + n];
            sC[j][n] = row[DINNER + DSTATE + n];
        }
        if (tid < 16) {
            int tau = cc*16 + tid;
            int orig = fw ? tau : (SEQLEN - 1 - tau);
            size_t di = ((size_t)s*SEQLEN + orig)*NHEADSN + h;
            sDec[tid] = dec[di];
            sDt[tid]  = dts[di];
        }
        __syncthreads();

        #pragma unroll 4
        for (int j = 0; j < 16; j++) {
            float d  = sDec[j];
            float dtv = sDt[j];
            float dtx = dtv * sX[j][p];
            const float4* B4 = (const float4*)&sB[j][q << 4];
            const float4* C4 = (const float4*)&sC[j][q << 4];
            float ysum = 0.f;
            #pragma unroll
            for (int v = 0; v < 4; v++) {
                float4 bb = B4[v], cv = C4[v];
                hreg[v*4+0] = fmaf(hreg[v*4+0], d, dtx*bb.x); ysum = fmaf(hreg[v*4+0], cv.x, ysum);
                hreg[v*4+1] = fmaf(hreg[v*4+1], d, dtx*bb.y); ysum = fmaf(hreg[v*4+1], cv.y, ysum);
                hreg[v*4+2] = fmaf(hreg[v*4+2], d, dtx*bb.z); ysum = fmaf(hreg[v*4+2], cv.z, ysum);
                hreg[v*4+3] = fmaf(hreg[v*4+3], d, dtx*bb.w); ysum = fmaf(hreg[v*4+3], cv.w, ysum);
            }
            ysum += __shfl_xor_sync(0xffffffffu, ysum, 1);
            ysum += __shfl_xor_sync(0xffffffffu, ysum, 2);
            if (q == 0) {
                int tau = cc*16 + j;
                int to = fw ? (tau + 1) : (SEQLEN - 2 - tau);
                if (to >= 0 && to < SEQLEN)
                    yout[(size_t)to*DINNER] = ysum;
            }
        }
        __syncthreads();
    }
}

// ---------------- gating + D skip + RMS norm (fp16 output) ----------------
__global__ void __launch_bounds__(256) gate_rms_kernel(
    const float* __restrict__ y, const float* __restrict__ xbc,
    const float* __restrict__ zx, const float* __restrict__ Dp,
    const float* __restrict__ rms_w, __half* __restrict__ out)
{
    int row = blockIdx.x;
    int b = row >> 11, t = row & 2047;
    int c = threadIdx.x << 2;
    size_t ybase = ((size_t)b*SEQLEN + t)*DINNER + c;
    const float4 yf = *(const float4*)&y[ybase];
    const float4 yb = *(const float4*)&y[ybase + (size_t)4*SEQLEN*DINNER];
    const float4 xo = *(const float4*)&xbc[((size_t)b*SEQLEN + t)*CONVDIM + c];
    const float4 zv = *(const float4*)&zx[((size_t)b*SEQLEN + t)*DINPROJ + c];
    float dp = Dp[c >> 6];
    float g0 = (yf.x + yb.x + xo.x*dp) * siluf(zv.x);
    float g1 = (yf.y + yb.y + xo.y*dp) * siluf(zv.y);
    float g2 = (yf.z + yb.z + xo.z*dp) * siluf(zv.z);
    float g3 = (yf.w + yb.w + xo.w*dp) * siluf(zv.w);
    float ss = g0*g0 + g1*g1 + g2*g2 + g3*g3;
    #pragma unroll
    for (int o = 16; o > 0; o >>= 1)
        ss += __shfl_xor_sync(0xffffffffu, ss, o);
    __shared__ float asum[8];
    int wid = threadIdx.x >> 5;
    if ((threadIdx.x & 31) == 0) asum[wid] = ss;
    __syncthreads();
    ss = asum[0]+asum[1]+asum[2]+asum[3]+asum[4]+asum[5]+asum[6]+asum[7];
    float scale = rsqrtf(ss * (1.0f/DINNER) + EPSV);
    const float4 wv = *(const float4*)&rms_w[c];
    __half2* op = (__half2*)(out + (size_t)row*DINNER + c);
    op[0] = __floats2half2_rn(g0*scale*wv.x, g1*scale*wv.y);
    op[1] = __floats2half2_rn(g2*scale*wv.z, g3*scale*wv.w);
}

// ---------------- launcher ----------------
extern "C" void kernel_launch(void* const* d_in, const int* in_sizes, int n_in,
                              void* d_out, int out_size)
{
    const float* x         = (const float*)d_in[0];
    const float* ln1_w     = (const float*)d_in[1];
    const float* ln1_b     = (const float*)d_in[2];
    const float* in_proj_w = (const float*)d_in[3];
    const float* conv_w    = (const float*)d_in[4];
    const float* conv_b    = (const float*)d_in[5];
    const float* dt_bias   = (const float*)d_in[6];
    const float* A_log     = (const float*)d_in[7];
    const float* Dp        = (const float*)d_in[8];
    const float* rms_w     = (const float*)d_in[9];
    const float* out_proj_w= (const float*)d_in[10];
    const float* ln2_w     = (const float*)d_in[11];
    const float* ln2_b     = (const float*)d_in[12];
    const float* fc1_w     = (const float*)d_in[13];
    const float* fc1_b     = (const float*)d_in[14];
    const float* fc2_w     = (const float*)d_in[15];
    const float* fc2_b     = (const float*)d_in[16];
    float* out = (float*)d_out;

    float *zx, *xbc, *dec, *dts, *y, *x2;
    __half *h16, *yg16, *ff1h, *wip, *wop, *w1, *w2;
    cudaGetSymbolAddress((void**)&zx,  g_zx);
    cudaGetSymbolAddress((void**)&xbc, g_xbc);
    cudaGetSymbolAddress((void**)&dec, g_dec);
    cudaGetSymbolAddress((void**)&dts, g_dts);
    cudaGetSymbolAddress((void**)&y,   g_y);
    cudaGetSymbolAddress((void**)&x2,  g_x2);
    cudaGetSymbolAddress((void**)&h16, g_h16);
    cudaGetSymbolAddress((void**)&yg16,g_yg16);
    cudaGetSymbolAddress((void**)&ff1h,g_ff1h);
    cudaGetSymbolAddress((void**)&wip, g_wip);
    cudaGetSymbolAddress((void**)&wop, g_wop);
    cudaGetSymbolAddress((void**)&w1,  g_w1);
    cudaGetSymbolAddress((void**)&w2,  g_w2);

    cudaFuncSetAttribute(gemm_h<0,0>, cudaFuncAttributeMaxDynamicSharedMemorySize, GEMM_SMEM);
    cudaFuncSetAttribute(gemm_h<1,1>, cudaFuncAttributeMaxDynamicSharedMemorySize, GEMM_SMEM);
    cudaFuncSetAttribute(gemm_h<2,0>, cudaFuncAttributeMaxDynamicSharedMemorySize, GEMM_SMEM);
    cudaFuncSetAttribute(gemm_h<3,0>, cudaFuncAttributeMaxDynamicSharedMemorySize, GEMM_SMEM);

    // 0. weight conversions
    cvt_kernel<<<(DINPROJ*DMODEL)/1024, 256>>>(in_proj_w, wip, DINPROJ*DMODEL);
    cvt_kernel<<<(DMODEL*DINNER)/1024, 256>>>(out_proj_w, wop, DMODEL*DINNER);
    cvt_kernel<<<(DFF*DMODEL)/1024, 256>>>(fc1_w, w1, DFF*DMODEL);
    cvt_kernel<<<(DMODEL*DFF)/1024, 256>>>(fc2_w, w2, DMODEL*DFF);

    // 1. LN1 (fp16 out)
    ln_kernel<<<NROWS, 128>>>(x, ln1_w, ln1_b, h16);
    // 2. in_proj: [8192,512] @ [2208,512]^T
    gemm_h<0,0><<<dim3((DINPROJ + 127)/128, NROWS/128), 256, GEMM_SMEM>>>(
        h16, wip, nullptr, nullptr, zx, NROWS, DINPROJ, DMODEL);
    // 3. dt preprocess
    dt_kernel<<<(8*SEQLEN*NHEADSN)/256, 256>>>(zx, dt_bias, A_log, dec, dts);
    // 4. conv + silu
    conv_kernel<<<(NROWS*CONVDIM)/256, 256>>>(zx, conv_w, conv_b, xbc);
    // 5. bidirectional SSM scan
    scan_kernel<<<dim3(NHEADSN, 8), 256>>>(xbc, dec, dts, y);
    // 6. gate + D skip + RMS norm (fp16 out)
    gate_rms_kernel<<<NROWS, 256>>>(y, xbc, zx, Dp, rms_w, yg16);
    // 7. out_proj + residual(x): [8192,1024] @ [512,1024]^T
    gemm_h<2,0><<<dim3(DMODEL/128, NROWS/128), 256, GEMM_SMEM>>>(
        yg16, wop, nullptr, x, x2, NROWS, DMODEL, DINNER);
    // 8. LN2 (fp16 out)
    ln_kernel<<<NROWS, 128>>>(x2, ln2_w, ln2_b, h16);
    // 9. fc1 + bias + gelu (fp16 out): [8192,512] @ [2048,512]^T
    gemm_h<1,1><<<dim3(DFF/128, NROWS/128), 256, GEMM_SMEM>>>(
        h16, w1, fc1_b, nullptr, ff1h, NROWS, DFF, DMODEL);
    // 10. fc2 + bias + residual(x2): [8192,2048] @ [512,2048]^T -> d_out
    gemm_h<3,0><<<dim3(DMODEL/128, NROWS/128), 256, GEMM_SMEM>>>(
        ff1h, w2, fc2_b, x2, out, NROWS, DMODEL, DFF);
}